// round 10
// baseline (speedup 1.0000x reference)
#include <cuda_runtime.h>
#include <cuda_fp16.h>
#include <cstdint>

// out = IFFT( D .* FFT( A .* x ) ) per row, C = 4096, complex as (re,im) float pairs.
// A, D scale re/im independently (elementwise).
//
// 256 threads per row, ONE lane per thread (16 points), 64 regs, ~48% occupancy.
// 4096 = 16^3: three radix-16 register stages; two shared exchanges per direction
// staged in fp16 (__half2{re,im} = 4B entries), single aliased buffer.
// Variable twiddles come from per-CTA shared fp32 tables (built once per CTA):
//   T1[t][k] = w4096^{t(k+1)}, stride 17 -> conflict-free 8B LDS
//   T2[b][k] = w256^{b(k+1)}           -> broadcast reads
// Forward uses conjugate via free operand negation in the FFMA.

#define REV(c) ((((c) & 3) << 2) | ((c) >> 2))

__device__ __forceinline__ void cmul(float& r, float& i, float wr, float wi){
    float t = i * wi;
    float u = i * wr;
    float nr = fmaf(r, wr, -t);
    i = fmaf(r, wi, u);
    r = nr;
}
template<int DIR> __device__ __forceinline__ void mulj(float& r, float& i){
    float t = r;
    if (DIR < 0){ r = i;  i = -t; }
    else        { r = -i; i = t;  }
}
template<int DIR> __device__ __forceinline__ void cmulc(float& r, float& i, float cr, float ci_f){
    cmul(r, i, cr, (DIR < 0) ? ci_f : -ci_f);
}

#define TC1 0.92387953251128674f
#define TS1 0.38268343236508978f
#define TC2 0.70710678118654752f

template<int DIR>
__device__ __forceinline__ void fft4s(float& r0, float& i0, float& r1, float& i1,
                                      float& r2, float& i2, float& r3, float& i3){
    float t0r = r0 + r2, t0i = i0 + i2;
    float t1r = r0 - r2, t1i = i0 - i2;
    float t2r = r1 + r3, t2i = i1 + i3;
    float t3r, t3i;
    if (DIR < 0){ t3r = i1 - i3; t3i = r3 - r1; }
    else        { t3r = i3 - i1; t3i = r1 - r3; }
    r0 = t0r + t2r; i0 = t0i + t2i;
    r2 = t0r - t2r; i2 = t0i - t2i;
    r1 = t1r + t3r; i1 = t1i + t3i;
    r3 = t1r - t3r; i3 = t1i - t3i;
}

template<int DIR>
__device__ __forceinline__ void fft16_nat(float r[16], float i[16]){
    fft4s<DIR>(r[0],i[0], r[4],i[4], r[8], i[8],  r[12],i[12]);
    fft4s<DIR>(r[1],i[1], r[5],i[5], r[9], i[9],  r[13],i[13]);
    fft4s<DIR>(r[2],i[2], r[6],i[6], r[10],i[10], r[14],i[14]);
    fft4s<DIR>(r[3],i[3], r[7],i[7], r[11],i[11], r[15],i[15]);
    cmulc<DIR>(r[5], i[5],  TC1, -TS1);
    cmulc<DIR>(r[9], i[9],  TC2, -TC2);
    cmulc<DIR>(r[13],i[13], TS1, -TC1);
    cmulc<DIR>(r[6], i[6],  TC2, -TC2);
    mulj<DIR>(r[10],i[10]);
    cmulc<DIR>(r[14],i[14],-TC2, -TC2);
    cmulc<DIR>(r[7], i[7],  TS1, -TC1);
    cmulc<DIR>(r[11],i[11],-TC2, -TC2);
    cmulc<DIR>(r[15],i[15],-TC1,  TS1);
    fft4s<DIR>(r[0], i[0],  r[1], i[1],  r[2], i[2],  r[3], i[3]);
    fft4s<DIR>(r[4], i[4],  r[5], i[5],  r[6], i[6],  r[7], i[7]);
    fft4s<DIR>(r[8], i[8],  r[9], i[9],  r[10],i[10], r[11],i[11]);
    fft4s<DIR>(r[12],i[12], r[13],i[13], r[14],i[14], r[15],i[15]);
}

template<int DIR>
__device__ __forceinline__ void fft16_rev(float r[16], float i[16]){
    fft4s<DIR>(r[0], i[0],  r[1], i[1],  r[2], i[2],  r[3], i[3]);
    fft4s<DIR>(r[4], i[4],  r[5], i[5],  r[6], i[6],  r[7], i[7]);
    fft4s<DIR>(r[8], i[8],  r[9], i[9],  r[10],i[10], r[11],i[11]);
    fft4s<DIR>(r[12],i[12], r[13],i[13], r[14],i[14], r[15],i[15]);
    cmulc<DIR>(r[5], i[5],  TC1, -TS1);
    cmulc<DIR>(r[6], i[6],  TC2, -TC2);
    cmulc<DIR>(r[7], i[7],  TS1, -TC1);
    cmulc<DIR>(r[9], i[9],  TC2, -TC2);
    mulj<DIR>(r[10],i[10]);
    cmulc<DIR>(r[11],i[11],-TC2, -TC2);
    cmulc<DIR>(r[13],i[13], TS1, -TC1);
    cmulc<DIR>(r[14],i[14],-TC2, -TC2);
    cmulc<DIR>(r[15],i[15],-TC1,  TS1);
    fft4s<DIR>(r[0],i[0], r[4],i[4], r[8], i[8],  r[12],i[12]);
    fft4s<DIR>(r[1],i[1], r[5],i[5], r[9], i[9],  r[13],i[13]);
    fft4s<DIR>(r[2],i[2], r[6],i[6], r[10],i[10], r[14],i[14]);
    fft4s<DIR>(r[3],i[3], r[7],i[7], r[11],i[11], r[15],i[15]);
}

// apply table twiddles: v[slot(k)] *= (w.x, DIR*w.y), k = 1..15, row[k-1] = w^k
template<int DIR, int RV>
__device__ __forceinline__ void twiddle_tab(float r[16], float i[16], const float2* __restrict__ row){
    #pragma unroll
    for (int k = 1; k < 16; ++k){
        const int slot = RV ? REV(k) : k;
        const float2 w = row[k - 1];
        cmul(r[slot], i[slot], w.x, (DIR < 0) ? -w.y : w.y);
    }
}

// build one table row: row[k-1] = (cos(k*theta), sin(k*theta)), k=1..15 (power chains)
__device__ __forceinline__ void build_row(float2* __restrict__ row, float theta){
    float sn, cs;
    __sincosf(theta, &sn, &cs);
    float w2r = fmaf(cs, cs, -(sn * sn));
    float w2i = 2.0f * cs * sn;
    float por = cs,  poi = sn;
    float per = w2r, pei = w2i;
    #pragma unroll
    for (int k = 1; k < 16; ++k){
        if (k & 1){
            row[k - 1] = make_float2(por, poi);
            if (k + 2 < 16) cmul(por, poi, w2r, w2i);
        } else {
            row[k - 1] = make_float2(per, pei);
            if (k + 2 < 16) cmul(per, pei, w2r, w2i);
        }
    }
}

#define S1H 258   // half2-entry stride for exchange-1 view
#define S2H 18    // half2-entry stride for exchange-2 view
#define TROW 17   // float2-entry table row stride -> conflict-free 8B LDS
#define D4096 1.5339807878856412e-3f   // 2*pi/4096
#define D256  2.4543692606170259e-2f   // 2*pi/256
#define INV_N (1.0f / 4096.0f)

#define T1_BYTES (256 * TROW * 8)            // 34,816
#define T2_BYTES (16 * TROW * 8)             // 2,176
#define EX_BYTES (256 * S2H * 4)             // 18,432 (covers s1 view: 16*258*4 = 16,512)
#define SMEM_TOTAL (T1_BYTES + T2_BYTES + EX_BYTES)   // 55,424

__global__ void __launch_bounds__(256, 4) afdf_fft10_kernel(
    const float2* __restrict__ x2,
    const float2* __restrict__ A2,
    const float2* __restrict__ D2,
    float2* __restrict__ out2)
{
    extern __shared__ __align__(16) char smem_raw[];
    float2*  const T1 = reinterpret_cast<float2*>(smem_raw);
    float2*  const T2 = reinterpret_cast<float2*>(smem_raw + T1_BYTES);
    __half2* const ex = reinterpret_cast<__half2*>(smem_raw + T1_BYTES + T2_BYTES);

    const int t    = threadIdx.x;      // 0..255
    const int c_lo = t & 15;
    const int b2   = t >> 4;           // 0..15
    const size_t base = (size_t)blockIdx.x * 4096;

    // ---- build twiddle tables (once per CTA) ----
    build_row(T1 + t * TROW, (float)t * D4096);
    if (t < 16) build_row(T2 + t * TROW, (float)t * D256);

    const float2* const t1row = T1 + t * TROW;
    const float2* const t2row = T2 + b2 * TROW;

    float r[16], i[16];

    // ---- load + A scale (elementwise re/im), points m = t + 256*a ----
    #pragma unroll
    for (int a = 0; a < 16; ++a){
        const int n = t + 256 * a;
        const float2 xv = x2[base + n];
        const float2 av = A2[n];
        r[a] = xv.x * av.x;
        i[a] = xv.y * av.y;
    }
    __syncthreads();                                     // B0: tables ready

    // ================= forward =================
    fft16_nat<-1>(r, i);                                 // U[c] at REV(c)
    twiddle_tab<-1, 1>(r, i, t1row);                     // * w4096^{-t c}
    #pragma unroll
    for (int c = 0; c < 16; ++c){
        const int s = REV(c);
        ex[c * S1H + t] = __floats2half2_rn(r[s], i[s]);
    }
    __syncthreads();                                     // B1
    #pragma unroll
    for (int a2 = 0; a2 < 16; ++a2){
        const float2 v = __half22float2(ex[c_lo * S1H + 16 * a2 + b2]);
        r[a2] = v.x; i[a2] = v.y;
    }
    fft16_nat<-1>(r, i);
    twiddle_tab<-1, 1>(r, i, t2row);                     // * w256^{-b2 c2}
    __syncthreads();                                     // B2 (alias: ex1 reads done)
    #pragma unroll
    for (int c2 = 0; c2 < 16; ++c2){
        const int s = REV(c2);
        ex[(c2 * 16 + c_lo) * S2H + b2] = __floats2half2_rn(r[s], i[s]);
    }
    __syncthreads();                                     // B3
    #pragma unroll
    for (int j = 0; j < 8; ++j){
        const uint2 u = *reinterpret_cast<const uint2*>(ex + t * S2H + 2 * j);
        const float2 v0 = __half22float2(*reinterpret_cast<const __half2*>(&u.x));
        const float2 v1 = __half22float2(*reinterpret_cast<const __half2*>(&u.y));
        r[2*j]   = v0.x; i[2*j]   = v0.y;
        r[2*j+1] = v1.x; i[2*j+1] = v1.y;
    }
    fft16_nat<-1>(r, i);
    // now F[256*d2 + t] sits at slot REV(d2)

    // ---- D scale (1/N folded) ----
    #pragma unroll
    for (int d2 = 0; d2 < 16; ++d2){
        const float2 dv = D2[t + 256 * d2];
        const int s = REV(d2);
        r[s] *= dv.x * INV_N;
        i[s] *= dv.y * INV_N;
    }
    __syncthreads();                                     // B4 (alias: ex2 reads done)

    // ================= inverse =================
    fft16_rev<1>(r, i);                                  // REV in -> natural out
    twiddle_tab<1, 0>(r, i, t1row);
    #pragma unroll
    for (int c = 0; c < 16; ++c){
        ex[c * S1H + t] = __floats2half2_rn(r[c], i[c]);
    }
    __syncthreads();                                     // B5
    #pragma unroll
    for (int a2 = 0; a2 < 16; ++a2){
        const float2 v = __half22float2(ex[c_lo * S1H + 16 * a2 + b2]);
        r[a2] = v.x; i[a2] = v.y;
    }
    fft16_nat<1>(r, i);
    twiddle_tab<1, 1>(r, i, t2row);
    __syncthreads();                                     // B6 (alias: ex1 reads done)
    #pragma unroll
    for (int c2 = 0; c2 < 16; ++c2){
        const int s = REV(c2);
        ex[(c2 * 16 + c_lo) * S2H + b2] = __floats2half2_rn(r[s], i[s]);
    }
    __syncthreads();                                     // B7
    #pragma unroll
    for (int j = 0; j < 8; ++j){
        const uint2 u = *reinterpret_cast<const uint2*>(ex + t * S2H + 2 * j);
        const float2 v0 = __half22float2(*reinterpret_cast<const __half2*>(&u.x));
        const float2 v1 = __half22float2(*reinterpret_cast<const __half2*>(&u.y));
        r[2*j]   = v0.x; i[2*j]   = v0.y;
        r[2*j+1] = v1.x; i[2*j+1] = v1.y;
    }
    fft16_nat<1>(r, i);
    // out[256*d2 + t] at slot REV(d2)

    // ---- store ----
    #pragma unroll
    for (int d2 = 0; d2 < 16; ++d2){
        const int s = REV(d2);
        out2[base + t + 256 * d2] = make_float2(r[s], i[s]);
    }
}

extern "C" void kernel_launch(void* const* d_in, const int* in_sizes, int n_in,
                              void* d_out, int out_size)
{
    const float2* x2 = (const float2*)d_in[0];
    const float2* A2 = (const float2*)d_in[1];
    const float2* D2 = (const float2*)d_in[2];
    float2* out2 = (float2*)d_out;

    cudaFuncSetAttribute(afdf_fft10_kernel,
                         cudaFuncAttributeMaxDynamicSharedMemorySize, SMEM_TOTAL);

    const int rows = in_sizes[0] / (4096 * 2);
    afdf_fft10_kernel<<<rows, 256, SMEM_TOTAL>>>(x2, A2, D2, out2);
}

// round 12
// speedup vs baseline: 1.0517x; 1.0517x over previous
#include <cuda_runtime.h>
#include <cuda_fp16.h>
#include <cstdint>

// out = IFFT( D .* FFT( A .* x ) ) per row, C = 4096, complex as (re,im) float pairs.
// A, D scale re/im independently (elementwise).
//
// TWO rows per CTA, 256 threads; each thread owns point-set t for both rows
// (rows 2*bid, 2*bid+1). Twiddle chains / sincos / A / D / addressing are
// row-invariant -> computed once, applied to both rows. Exchange entries pack
// both rows as fp16: uint2{ half2(reA,imA), half2(reB,imB) } = 8B -> same
// slot count as one fp32 row, half the slots per row. Strides 257 / 17 are
// conflict-free for 8B accesses (same indexing as the verified R8 kernel).
// Single aliased exchange buffer, 7 barriers.

#define REV(c) ((((c) & 3) << 2) | ((c) >> 2))

__device__ __forceinline__ void cmul(float& r, float& i, float wr, float wi){
    float t = i * wi;
    float u = i * wr;
    float nr = fmaf(r, wr, -t);
    i = fmaf(r, wi, u);
    r = nr;
}
template<int DIR> __device__ __forceinline__ void mulj(float& r, float& i){
    float t = r;
    if (DIR < 0){ r = i;  i = -t; }
    else        { r = -i; i = t;  }
}
template<int DIR> __device__ __forceinline__ void cmulc(float& r, float& i, float cr, float ci_f){
    cmul(r, i, cr, (DIR < 0) ? ci_f : -ci_f);
}

#define TC1 0.92387953251128674f
#define TS1 0.38268343236508978f
#define TC2 0.70710678118654752f

template<int DIR>
__device__ __forceinline__ void fft4s(float& r0, float& i0, float& r1, float& i1,
                                      float& r2, float& i2, float& r3, float& i3){
    float t0r = r0 + r2, t0i = i0 + i2;
    float t1r = r0 - r2, t1i = i0 - i2;
    float t2r = r1 + r3, t2i = i1 + i3;
    float t3r, t3i;
    if (DIR < 0){ t3r = i1 - i3; t3i = r3 - r1; }
    else        { t3r = i3 - i1; t3i = r1 - r3; }
    r0 = t0r + t2r; i0 = t0i + t2i;
    r2 = t0r - t2r; i2 = t0i - t2i;
    r1 = t1r + t3r; i1 = t1i + t3i;
    r3 = t1r - t3r; i3 = t1i - t3i;
}

template<int DIR>
__device__ __forceinline__ void fft16_nat(float r[16], float i[16]){
    fft4s<DIR>(r[0],i[0], r[4],i[4], r[8], i[8],  r[12],i[12]);
    fft4s<DIR>(r[1],i[1], r[5],i[5], r[9], i[9],  r[13],i[13]);
    fft4s<DIR>(r[2],i[2], r[6],i[6], r[10],i[10], r[14],i[14]);
    fft4s<DIR>(r[3],i[3], r[7],i[7], r[11],i[11], r[15],i[15]);
    cmulc<DIR>(r[5], i[5],  TC1, -TS1);
    cmulc<DIR>(r[9], i[9],  TC2, -TC2);
    cmulc<DIR>(r[13],i[13], TS1, -TC1);
    cmulc<DIR>(r[6], i[6],  TC2, -TC2);
    mulj<DIR>(r[10],i[10]);
    cmulc<DIR>(r[14],i[14],-TC2, -TC2);
    cmulc<DIR>(r[7], i[7],  TS1, -TC1);
    cmulc<DIR>(r[11],i[11],-TC2, -TC2);
    cmulc<DIR>(r[15],i[15],-TC1,  TS1);
    fft4s<DIR>(r[0], i[0],  r[1], i[1],  r[2], i[2],  r[3], i[3]);
    fft4s<DIR>(r[4], i[4],  r[5], i[5],  r[6], i[6],  r[7], i[7]);
    fft4s<DIR>(r[8], i[8],  r[9], i[9],  r[10],i[10], r[11],i[11]);
    fft4s<DIR>(r[12],i[12], r[13],i[13], r[14],i[14], r[15],i[15]);
}

template<int DIR>
__device__ __forceinline__ void fft16_rev(float r[16], float i[16]){
    fft4s<DIR>(r[0], i[0],  r[1], i[1],  r[2], i[2],  r[3], i[3]);
    fft4s<DIR>(r[4], i[4],  r[5], i[5],  r[6], i[6],  r[7], i[7]);
    fft4s<DIR>(r[8], i[8],  r[9], i[9],  r[10],i[10], r[11],i[11]);
    fft4s<DIR>(r[12],i[12], r[13],i[13], r[14],i[14], r[15],i[15]);
    cmulc<DIR>(r[5], i[5],  TC1, -TS1);
    cmulc<DIR>(r[6], i[6],  TC2, -TC2);
    cmulc<DIR>(r[7], i[7],  TS1, -TC1);
    cmulc<DIR>(r[9], i[9],  TC2, -TC2);
    mulj<DIR>(r[10],i[10]);
    cmulc<DIR>(r[11],i[11],-TC2, -TC2);
    cmulc<DIR>(r[13],i[13], TS1, -TC1);
    cmulc<DIR>(r[14],i[14],-TC2, -TC2);
    cmulc<DIR>(r[15],i[15],-TC1,  TS1);
    fft4s<DIR>(r[0],i[0], r[4],i[4], r[8], i[8],  r[12],i[12]);
    fft4s<DIR>(r[1],i[1], r[5],i[5], r[9], i[9],  r[13],i[13]);
    fft4s<DIR>(r[2],i[2], r[6],i[6], r[10],i[10], r[14],i[14]);
    fft4s<DIR>(r[3],i[3], r[7],i[7], r[11],i[11], r[15],i[15]);
}

// shared-chain twiddle stage applied to TWO row arrays (same theta for both)
template<int DIR, int RV>
__device__ __forceinline__ void twiddle2(float rA[16], float iA[16],
                                         float rB[16], float iB[16], float theta){
    float sn, cs;
    __sincosf(theta, &sn, &cs);
    if (DIR < 0) sn = -sn;
    float w2r = fmaf(cs, cs, -(sn * sn));
    float w2i = 2.0f * cs * sn;
    float por = cs,  poi = sn;
    float per = w2r, pei = w2i;
    #pragma unroll
    for (int k = 1; k < 16; ++k){
        const int slot = RV ? REV(k) : k;
        if (k & 1){
            cmul(rA[slot], iA[slot], por, poi);
            cmul(rB[slot], iB[slot], por, poi);
            if (k + 2 < 16) cmul(por, poi, w2r, w2i);
        } else {
            cmul(rA[slot], iA[slot], per, pei);
            cmul(rB[slot], iB[slot], per, pei);
            if (k + 2 < 16) cmul(per, pei, w2r, w2i);
        }
    }
}

// fp16 bit-pack helpers (toolkit-portable: go through __half2_raw)
__device__ __forceinline__ uint32_t h2_bits(__half2 h){
    const __half2_raw hr = *reinterpret_cast<const __half2_raw*>(&h);
    return (uint32_t)hr.x | ((uint32_t)hr.y << 16);
}
__device__ __forceinline__ __half2 bits_h2(uint32_t b){
    __half2_raw hr;
    hr.x = (unsigned short)(b & 0xFFFFu);
    hr.y = (unsigned short)(b >> 16);
    return *reinterpret_cast<__half2*>(&hr);
}

__device__ __forceinline__ uint2 pack2(float rA, float iA, float rB, float iB){
    uint2 e;
    e.x = h2_bits(__floats2half2_rn(rA, iA));
    e.y = h2_bits(__floats2half2_rn(rB, iB));
    return e;
}
__device__ __forceinline__ void unpack2(uint2 e, float& rA, float& iA, float& rB, float& iB){
    const float2 a = __half22float2(bits_h2(e.x));
    const float2 b = __half22float2(bits_h2(e.y));
    rA = a.x; iA = a.y; rB = b.x; iB = b.y;
}

#define S1R 257   // 8B-entry stride; conflict-free (same indexing as fp32 R8 kernel)
#define S2R 17
#define D4096 1.5339807878856412e-3f   // 2*pi/4096
#define D256  2.4543692606170259e-2f   // 2*pi/256
#define INV_N (1.0f / 4096.0f)

__global__ void __launch_bounds__(256, 2) afdf_fft11_kernel(
    const float2* __restrict__ x2,
    const float2* __restrict__ A2,
    const float2* __restrict__ D2,
    float2* __restrict__ out2)
{
    // aliased views: ex1 = 16 x 257 (4112 entries), ex2 = 256 x 17 (4352 entries)
    __shared__ __align__(16) uint2 sb[256 * S2R];   // 34,816 B

    const int t    = threadIdx.x;      // 0..255
    const int c_lo = t & 15;
    const int b2   = t >> 4;           // 0..15
    const size_t base0 = (size_t)blockIdx.x * 8192;         // row pair base (float2)
    const size_t base1 = base0 + 4096;

    float rA[16], iA[16], rB[16], iB[16];

    // ---- load + A scale (A shared across both rows) ----
    #pragma unroll
    for (int a = 0; a < 16; ++a){
        const int n = t + 256 * a;
        const float2 av = A2[n];
        const float2 x0 = x2[base0 + n];
        const float2 x1 = x2[base1 + n];
        rA[a] = x0.x * av.x;  iA[a] = x0.y * av.y;
        rB[a] = x1.x * av.x;  iB[a] = x1.y * av.y;
    }

    // ================= forward =================
    fft16_nat<-1>(rA, iA);
    fft16_nat<-1>(rB, iB);
    twiddle2<-1, 1>(rA, iA, rB, iB, (float)t * D4096);
    #pragma unroll
    for (int c = 0; c < 16; ++c){
        const int s = REV(c);
        sb[c * S1R + t] = pack2(rA[s], iA[s], rB[s], iB[s]);
    }
    __syncthreads();                                     // B1
    #pragma unroll
    for (int a2 = 0; a2 < 16; ++a2){
        unpack2(sb[c_lo * S1R + 16 * a2 + b2], rA[a2], iA[a2], rB[a2], iB[a2]);
    }
    fft16_nat<-1>(rA, iA);
    fft16_nat<-1>(rB, iB);
    twiddle2<-1, 1>(rA, iA, rB, iB, (float)b2 * D256);
    __syncthreads();                                     // B2 (alias: ex1 reads done)
    #pragma unroll
    for (int c2 = 0; c2 < 16; ++c2){
        const int s = REV(c2);
        sb[(c2 * 16 + c_lo) * S2R + b2] = pack2(rA[s], iA[s], rB[s], iB[s]);
    }
    __syncthreads();                                     // B3
    #pragma unroll
    for (int b = 0; b < 16; ++b){
        unpack2(sb[t * S2R + b], rA[b], iA[b], rB[b], iB[b]);
    }
    fft16_nat<-1>(rA, iA);
    fft16_nat<-1>(rB, iB);
    // F[256*d2 + t] at slot REV(d2) for both rows

    // ---- D scale (shared across rows; 1/N folded) ----
    #pragma unroll
    for (int d2 = 0; d2 < 16; ++d2){
        const float2 dv = D2[t + 256 * d2];
        const float dsx = dv.x * INV_N;
        const float dsy = dv.y * INV_N;
        const int s = REV(d2);
        rA[s] *= dsx;  iA[s] *= dsy;
        rB[s] *= dsx;  iB[s] *= dsy;
    }
    __syncthreads();                                     // B4 (alias: ex2 reads done)

    // ================= inverse =================
    fft16_rev<1>(rA, iA);
    fft16_rev<1>(rB, iB);
    twiddle2<1, 0>(rA, iA, rB, iB, (float)t * D4096);
    #pragma unroll
    for (int c = 0; c < 16; ++c){
        sb[c * S1R + t] = pack2(rA[c], iA[c], rB[c], iB[c]);
    }
    __syncthreads();                                     // B5
    #pragma unroll
    for (int a2 = 0; a2 < 16; ++a2){
        unpack2(sb[c_lo * S1R + 16 * a2 + b2], rA[a2], iA[a2], rB[a2], iB[a2]);
    }
    fft16_nat<1>(rA, iA);
    fft16_nat<1>(rB, iB);
    twiddle2<1, 1>(rA, iA, rB, iB, (float)b2 * D256);
    __syncthreads();                                     // B6 (alias: ex1 reads done)
    #pragma unroll
    for (int c2 = 0; c2 < 16; ++c2){
        const int s = REV(c2);
        sb[(c2 * 16 + c_lo) * S2R + b2] = pack2(rA[s], iA[s], rB[s], iB[s]);
    }
    __syncthreads();                                     // B7
    #pragma unroll
    for (int b = 0; b < 16; ++b){
        unpack2(sb[t * S2R + b], rA[b], iA[b], rB[b], iB[b]);
    }
    fft16_nat<1>(rA, iA);
    fft16_nat<1>(rB, iB);
    // out[256*d2 + t] at slot REV(d2)

    // ---- store both rows ----
    #pragma unroll
    for (int d2 = 0; d2 < 16; ++d2){
        const int s = REV(d2);
        out2[base0 + t + 256 * d2] = make_float2(rA[s], iA[s]);
        out2[base1 + t + 256 * d2] = make_float2(rB[s], iB[s]);
    }
}

extern "C" void kernel_launch(void* const* d_in, const int* in_sizes, int n_in,
                              void* d_out, int out_size)
{
    const float2* x2 = (const float2*)d_in[0];
    const float2* A2 = (const float2*)d_in[1];
    const float2* D2 = (const float2*)d_in[2];
    float2* out2 = (float2*)d_out;

    const int rows = in_sizes[0] / (4096 * 2);
    afdf_fft11_kernel<<<rows / 2, 256>>>(x2, A2, D2, out2);
}